// round 5
// baseline (speedup 1.0000x reference)
#include <cuda_runtime.h>
#include <math.h>

#define NSIZE 96
#define MTOT  (NSIZE * NSIZE)        // 9216
#define GDIM  (2 * NSIZE - 1)        // 191
#define CHUNKS 8
#define CROWS  (NSIZE / CHUNKS)      // 12 source rows per block

// Physics constants (match reference)
#define WAVELEN 1.55e-6
#define DZ      1.0e-5

// Scratch in __device__ globals (no allocations allowed)
__device__ float2 d_modes[MTOT];
__device__ float2 d_G[GDIM * GDIM];
__device__ float2 d_part[CHUNKS * MTOT];
__device__ float2 d_result[MTOT];

// ---------------------------------------------------------------------------
// modes[i] = x[i] * exp(j * w[i])
// ---------------------------------------------------------------------------
__global__ void prep_modes(const float* __restrict__ x,
                           const float* __restrict__ w) {
    int i = blockIdx.x * blockDim.x + threadIdx.x;
    if (i < MTOT) {
        float s, c;
        sincosf(w[i], &s, &c);
        float xv = x[i];
        d_modes[i] = make_float2(xv * c, xv * s);
    }
}

// ---------------------------------------------------------------------------
// G table: G[da+95][db+95] = (dz/r^2)(1/(2*pi*r) + 1/(j*lambda)) e^{jkr} * dA
// Uniform grid -> r depends only on index differences. fp64 for exact phase.
// ---------------------------------------------------------------------------
__global__ void prep_G(const float* __restrict__ xc,
                       const float* __restrict__ yc) {
    int t = blockIdx.x * blockDim.x + threadIdx.x;
    if (t >= GDIM * GDIM) return;
    int ia = t / GDIM;
    int ib = t - ia * GDIM;
    int da = ia - (NSIZE - 1);
    int db = ib - (NSIZE - 1);
    int a1 = da > 0 ? da : 0;  int a2 = a1 - da;
    int b1 = db > 0 ? db : 0;  int b2 = b1 - db;
    double dx = (double)xc[a1] - (double)xc[a2];
    double dy = (double)yc[b1] - (double)yc[b2];
    const double dz  = DZ;
    const double lam = WAVELEN;
    double r2 = dx * dx + dy * dy + dz * dz;
    double r  = sqrt(r2);
    double kk = 2.0 * M_PI / lam;
    double s, c;
    sincos(kk * r, &s, &c);
    double ar = dz / (2.0 * M_PI * r2 * r);   // real amplitude
    double ai = -dz / (r2 * lam);             // 1/(j*lam) = -j/lam
    const double dA = (1.55e-6) * (1.55e-6);
    double gr = (ar * c - ai * s) * dA;
    double gi = (ar * s + ai * c) * dA;
    d_G[t] = make_float2((float)gr, (float)gi);
}

// ---------------------------------------------------------------------------
// 2D full correlation: out[aj,bj] = sum_{ai,bi} modes[ai,bi]*G[ai-aj+95,bi-bj+95]
// ---------------------------------------------------------------------------
__global__ void __launch_bounds__(NSIZE) corr_kernel() {
    __shared__ float2 sm[CROWS * NSIZE];   // modes slab  (12x96)
    __shared__ float2 sg[CROWS * GDIM];    // G window    (12x191)

    int aj = blockIdx.x;
    int ch = blockIdx.y;
    int bj = threadIdx.x;
    int ai0 = ch * CROWS;

    for (int t = bj; t < CROWS * NSIZE; t += NSIZE)
        sm[t] = d_modes[ai0 * NSIZE + t];

    int grow0 = ai0 - aj + (NSIZE - 1);
    for (int t = bj; t < CROWS * GDIM; t += NSIZE) {
        int ci = t / GDIM;
        int cc = t - ci * GDIM;
        sg[t] = d_G[(grow0 + ci) * GDIM + cc];
    }
    __syncthreads();

    float re = 0.0f, im = 0.0f;
    #pragma unroll
    for (int ci = 0; ci < CROWS; ci++) {
        const float2* __restrict__ mrow = &sm[ci * NSIZE];
        const float2* __restrict__ grow = &sg[ci * GDIM + (NSIZE - 1) - bj];
        #pragma unroll 8
        for (int bi = 0; bi < NSIZE; bi++) {
            float2 m = mrow[bi];
            float2 g = grow[bi];
            re = fmaf(m.x, g.x, re);
            re = fmaf(-m.y, g.y, re);
            im = fmaf(m.x, g.y, im);
            im = fmaf(m.y, g.x, im);
        }
    }
    d_part[ch * MTOT + aj * NSIZE + bj] = make_float2(re, im);
}

// ---------------------------------------------------------------------------
// Reduce chunk partials into d_result (complex, logical layout).
// ---------------------------------------------------------------------------
__global__ void reduce_kernel() {
    int j = blockIdx.x * blockDim.x + threadIdx.x;
    if (j < MTOT) {
        float re = 0.0f, im = 0.0f;
        #pragma unroll
        for (int ch = 0; ch < CHUNKS; ch++) {
            float2 p = d_part[ch * MTOT + j];
            re += p.x;
            im += p.y;
        }
        d_result[j] = make_float2(re, im);
    }
}

// ---------------------------------------------------------------------------
// Output formatting probes. Interleaved (float2) was falsified in rounds 1-4
// (rel_err = sqrt(2) with magnitude preserved => layout-class mismatch).
//   mode 0: planar  [Re(0..M-1), Im(0..M-1)]   (out_size == 2*MTOT)
//   mode 1: real part only                     (out_size == MTOT)
//   mode 2: interleaved fallback
// ---------------------------------------------------------------------------
__global__ void format_planar(float* __restrict__ out) {
    int j = blockIdx.x * blockDim.x + threadIdx.x;
    if (j < MTOT) {
        float2 v = d_result[j];
        out[j]        = v.x;
        out[MTOT + j] = v.y;
    }
}
__global__ void format_real(float* __restrict__ out) {
    int j = blockIdx.x * blockDim.x + threadIdx.x;
    if (j < MTOT) out[j] = d_result[j].x;
}
__global__ void format_interleaved(float2* __restrict__ out) {
    int j = blockIdx.x * blockDim.x + threadIdx.x;
    if (j < MTOT) out[j] = d_result[j];
}

extern "C" void kernel_launch(void* const* d_in, const int* in_sizes, int n_in,
                              void* d_out, int out_size) {
    const float* x  = (const float*)d_in[0];
    const float* w  = (const float*)d_in[1];
    const float* xc = (const float*)d_in[2];
    const float* yc = (const float*)d_in[3];

    prep_modes<<<(MTOT + 255) / 256, 256>>>(x, w);
    prep_G<<<(GDIM * GDIM + 255) / 256, 256>>>(xc, yc);
    corr_kernel<<<dim3(NSIZE, CHUNKS), NSIZE>>>();
    reduce_kernel<<<(MTOT + 255) / 256, 256>>>();

    int blocks = (MTOT + 255) / 256;
    if (out_size == 2 * MTOT) {
        // float32 buffer of 18432: interleaved already failed -> try planar
        format_planar<<<blocks, 256>>>((float*)d_out);
    } else if (out_size == MTOT) {
        // 9216 elements: complex64-interleaved already failed -> try real-only
        format_real<<<blocks, 256>>>((float*)d_out);
    } else {
        format_interleaved<<<blocks, 256>>>((float2*)d_out);
    }
}

// round 6
// speedup vs baseline: 1.5171x; 1.5171x over previous
#include <cuda_runtime.h>
#include <math.h>

#define NSIZE 96
#define MTOT  (NSIZE * NSIZE)        // 9216
#define GDIM  (2 * NSIZE - 1)        // 191
#define GTOT  (GDIM * GDIM)          // 36481
#define CHUNKS 16
#define CROWS  (NSIZE / CHUNKS)      // 6 source rows per block
#define AJT    4                     // aj values per block (one per warp)
#define GROWS  (CROWS + AJT - 1)     // 9 staged G rows

// Physics constants (match reference)
#define WAVELEN 1.55e-6
#define DZ      1.0e-5

// Scratch in __device__ globals (no allocations allowed)
__device__ float2 d_modes[MTOT];
__device__ float2 d_G[GTOT];
__device__ float2 d_part[CHUNKS * MTOT];

// ---------------------------------------------------------------------------
// Fused prep: modes[i] = x[i]*exp(j*w[i])  and  G difference table (fp64).
// ---------------------------------------------------------------------------
__global__ void prep_fused(const float* __restrict__ x,
                           const float* __restrict__ w,
                           const float* __restrict__ xc,
                           const float* __restrict__ yc) {
    int i = blockIdx.x * blockDim.x + threadIdx.x;
    if (i < MTOT) {
        float s, c;
        sincosf(w[i], &s, &c);
        float xv = x[i];
        d_modes[i] = make_float2(xv * c, xv * s);
    } else {
        int t = i - MTOT;
        if (t >= GTOT) return;
        int ia = t / GDIM;
        int ib = t - ia * GDIM;
        int da = ia - (NSIZE - 1);
        int db = ib - (NSIZE - 1);
        int a1 = da > 0 ? da : 0;  int a2 = a1 - da;
        int b1 = db > 0 ? db : 0;  int b2 = b1 - db;
        double dx = (double)xc[a1] - (double)xc[a2];
        double dy = (double)yc[b1] - (double)yc[b2];
        const double dz  = DZ;
        const double lam = WAVELEN;
        double r2 = dx * dx + dy * dy + dz * dz;
        double r  = sqrt(r2);
        double s, c;
        sincos((2.0 * M_PI / lam) * r, &s, &c);
        double ar = dz / (2.0 * M_PI * r2 * r);
        double ai = -dz / (r2 * lam);
        const double dA = (1.55e-6) * (1.55e-6);
        d_G[t] = make_float2((float)((ar * c - ai * s) * dA),
                             (float)((ar * s + ai * c) * dA));
    }
}

// ---------------------------------------------------------------------------
// Correlation: out[aj,bj] = sum_{ai,bi} modes[ai,bi] * G[ai-aj+95, bi-bj+95]
// Block = 128 threads: warp w handles aj = aj0 + w; each lane computes 3
// consecutive bj outputs with a sliding 3-deep register window over G, so
// only ONE new G value is loaded from smem per bi step (LDS traffic /3).
// ---------------------------------------------------------------------------
__global__ void __launch_bounds__(128) corr_kernel() {
    __shared__ float2 sm[CROWS * NSIZE];   // modes slab   (6 x 96)
    __shared__ float2 sg[GROWS * GDIM];    // G row window (9 x 191)

    int aj0 = blockIdx.x * AJT;
    int ai0 = blockIdx.y * CROWS;
    int tid = threadIdx.x;

    for (int t = tid; t < CROWS * NSIZE; t += 128)
        sm[t] = d_modes[ai0 * NSIZE + t];

    // staged rows row0..row0+8 always within [0, 190] for valid (ai0, aj0)
    int row0 = ai0 - aj0 + (NSIZE - 1) - (AJT - 1);
    for (int t = tid; t < GROWS * GDIM; t += 128) {
        int ci = t / GDIM;
        int cc = t - ci * GDIM;
        sg[t] = d_G[(row0 + ci) * GDIM + cc];
    }
    __syncthreads();

    int w    = tid >> 5;          // aj offset within block
    int lane = tid & 31;
    int bj0  = lane * 3;          // this lane's first output column

    float r0 = 0.f, i0 = 0.f, r1 = 0.f, i1 = 0.f, r2 = 0.f, i2 = 0.f;

    #pragma unroll
    for (int ci = 0; ci < CROWS; ci++) {
        const float2* __restrict__ mrow = &sm[ci * NSIZE];
        // warp w needs staged row ci + (AJT-1) - w; grow[bi] = col (bi-bj0+95)
        const float2* __restrict__ grow =
            &sg[(ci + (AJT - 1) - w) * GDIM + (NSIZE - 1) - bj0];
        float2 gm1 = grow[-1];   // col index >= 1  (bj0 <= 93)
        float2 gm2 = grow[-2];   // col index >= 0
        #pragma unroll 8
        for (int bi = 0; bi < NSIZE; bi++) {
            float2 g0 = grow[bi];     // one new G per step
            float2 m  = mrow[bi];     // warp-broadcast
            r0 = fmaf(m.x, g0.x,  r0); r0 = fmaf(-m.y, g0.y,  r0);
            i0 = fmaf(m.x, g0.y,  i0); i0 = fmaf( m.y, g0.x,  i0);
            r1 = fmaf(m.x, gm1.x, r1); r1 = fmaf(-m.y, gm1.y, r1);
            i1 = fmaf(m.x, gm1.y, i1); i1 = fmaf( m.y, gm1.x, i1);
            r2 = fmaf(m.x, gm2.x, r2); r2 = fmaf(-m.y, gm2.y, r2);
            i2 = fmaf(m.x, gm2.y, i2); i2 = fmaf( m.y, gm2.x, i2);
            gm2 = gm1; gm1 = g0;      // slide window (register rename)
        }
    }

    int base = blockIdx.y * MTOT + (aj0 + w) * NSIZE + bj0;
    d_part[base]     = make_float2(r0, i0);
    d_part[base + 1] = make_float2(r1, i1);
    d_part[base + 2] = make_float2(r2, i2);
}

// ---------------------------------------------------------------------------
// Fused reduce + output formatting (planar layout confirmed in round 5).
// ---------------------------------------------------------------------------
__global__ void reduce_planar(float* __restrict__ out) {
    int j = blockIdx.x * blockDim.x + threadIdx.x;
    if (j < MTOT) {
        float re = 0.f, im = 0.f;
        #pragma unroll
        for (int ch = 0; ch < CHUNKS; ch++) {
            float2 p = d_part[ch * MTOT + j];
            re += p.x; im += p.y;
        }
        out[j]        = re;
        out[MTOT + j] = im;
    }
}
__global__ void reduce_real(float* __restrict__ out) {
    int j = blockIdx.x * blockDim.x + threadIdx.x;
    if (j < MTOT) {
        float re = 0.f;
        #pragma unroll
        for (int ch = 0; ch < CHUNKS; ch++) re += d_part[ch * MTOT + j].x;
        out[j] = re;
    }
}
__global__ void reduce_interleaved(float2* __restrict__ out) {
    int j = blockIdx.x * blockDim.x + threadIdx.x;
    if (j < MTOT) {
        float re = 0.f, im = 0.f;
        #pragma unroll
        for (int ch = 0; ch < CHUNKS; ch++) {
            float2 p = d_part[ch * MTOT + j];
            re += p.x; im += p.y;
        }
        out[j] = make_float2(re, im);
    }
}

extern "C" void kernel_launch(void* const* d_in, const int* in_sizes, int n_in,
                              void* d_out, int out_size) {
    const float* x  = (const float*)d_in[0];
    const float* w  = (const float*)d_in[1];
    const float* xc = (const float*)d_in[2];
    const float* yc = (const float*)d_in[3];

    prep_fused<<<(MTOT + GTOT + 255) / 256, 256>>>(x, w, xc, yc);
    corr_kernel<<<dim3(NSIZE / AJT, CHUNKS), 128>>>();

    int blocks = (MTOT + 255) / 256;
    if (out_size == 2 * MTOT) {
        reduce_planar<<<blocks, 256>>>((float*)d_out);
    } else if (out_size == MTOT) {
        reduce_real<<<blocks, 256>>>((float*)d_out);
    } else {
        reduce_interleaved<<<blocks, 256>>>((float2*)d_out);
    }
}

// round 7
// speedup vs baseline: 1.7303x; 1.1405x over previous
#include <cuda_runtime.h>
#include <math.h>

#define NSIZE 96
#define MTOT  (NSIZE * NSIZE)        // 9216
#define GDIM  (2 * NSIZE - 1)        // 191
#define GTOT  (GDIM * GDIM)          // 36481
#define CHUNKS 16
#define CROWS  (NSIZE / CHUNKS)      // 6 source rows per block
#define AJT    4                     // aj values per block (one per warp)
#define GROWS  (CROWS + AJT - 1)     // 9 staged G rows

// Physics constants (match reference)
#define WAVELEN 1.55e-6
#define DZ      1.0e-5
#define TWO_PI  6.283185307179586476925286766559

// Scratch in __device__ globals (no allocations allowed)
__device__ float2 d_modes[MTOT];
__device__ float2 d_G[GTOT];
__device__ float2 d_part[CHUNKS * MTOT];

// ---------------------------------------------------------------------------
// Fused prep.
//  threads [0, MTOT):        modes[i] = x[i]*exp(j*w[i])
//  threads [MTOT, 2*MTOT):   one G QUADRANT entry (da,db in [0,95]); G depends
//    only on (|da|,|db|) so each thread mirror-writes 4 table positions.
//  Phase k*r computed in double (cheap mul/fma + dsqrt), range-reduced mod 2pi
//  in double, then evaluated with HW fp32 sincosf -- no fp64 sincos.
// ---------------------------------------------------------------------------
__global__ void prep_fused(const float* __restrict__ x,
                           const float* __restrict__ w,
                           const float* __restrict__ xc,
                           const float* __restrict__ yc) {
    int i = blockIdx.x * blockDim.x + threadIdx.x;
    if (i < MTOT) {
        float s, c;
        sincosf(w[i], &s, &c);
        float xv = x[i];
        d_modes[i] = make_float2(xv * c, xv * s);
        return;
    }
    int t = i - MTOT;
    if (t >= MTOT) return;
    int da = t / NSIZE;              // 0..95
    int db = t - da * NSIZE;         // 0..95

    double dx = (double)xc[da] - (double)xc[0];
    double dy = (double)yc[db] - (double)yc[0];
    const double dz  = DZ;
    const double lam = WAVELEN;
    double r2 = dx * dx + dy * dy + dz * dz;
    double r  = sqrt(r2);

    // phase = k*r, reduced to [0, 2pi) in double, evaluated in fp32
    double phase = (TWO_PI / lam) * r;
    double ph = phase - TWO_PI * trunc(phase * (1.0 / TWO_PI));
    float s, c;
    sincosf((float)ph, &s, &c);

    double ar = dz / (TWO_PI * r2 * r);     // real amplitude
    double ai = -dz / (r2 * lam);           // 1/(j*lam) = -j/lam
    const double dA = (1.55e-6) * (1.55e-6);
    float gr = (float)((ar * (double)c - ai * (double)s) * dA);
    float gi = (float)((ar * (double)s + ai * (double)c) * dA);
    float2 g = make_float2(gr, gi);

    // mirror to the 4 symmetric positions (dups when da==0 or db==0 harmless)
    int rp = (NSIZE - 1) + da, rm = (NSIZE - 1) - da;
    int cp = (NSIZE - 1) + db, cm = (NSIZE - 1) - db;
    d_G[rp * GDIM + cp] = g;
    d_G[rp * GDIM + cm] = g;
    d_G[rm * GDIM + cp] = g;
    d_G[rm * GDIM + cm] = g;
}

// ---------------------------------------------------------------------------
// Correlation: out[aj,bj] = sum_{ai,bi} modes[ai,bi] * G[ai-aj+95, bi-bj+95]
// Block = 128 threads: warp w handles aj = aj0 + w; each lane computes 3
// consecutive bj with a sliding 3-deep register window over G (one new G
// LDS.64 per bi step); modes fetched as broadcast LDS.128 per 2 steps.
// ---------------------------------------------------------------------------
__global__ void __launch_bounds__(128) corr_kernel() {
    __shared__ __align__(16) float2 sm[CROWS * NSIZE];   // modes slab (6x96)
    __shared__ float2 sg[GROWS * GDIM];                  // G window   (9x191)

    int aj0 = blockIdx.x * AJT;
    int ai0 = blockIdx.y * CROWS;
    int tid = threadIdx.x;

    for (int t = tid; t < CROWS * NSIZE; t += 128)
        sm[t] = d_modes[ai0 * NSIZE + t];

    int row0 = ai0 - aj0 + (NSIZE - 1) - (AJT - 1);
    for (int t = tid; t < GROWS * GDIM; t += 128) {
        int ci = t / GDIM;
        int cc = t - ci * GDIM;
        sg[t] = d_G[(row0 + ci) * GDIM + cc];
    }
    __syncthreads();

    int w    = tid >> 5;
    int lane = tid & 31;
    int bj0  = lane * 3;

    float r0 = 0.f, i0 = 0.f, r1 = 0.f, i1 = 0.f, r2 = 0.f, i2 = 0.f;

    #pragma unroll
    for (int ci = 0; ci < CROWS; ci++) {
        const float4* __restrict__ mrow4 =
            (const float4*)&sm[ci * NSIZE];
        const float2* __restrict__ grow =
            &sg[(ci + (AJT - 1) - w) * GDIM + (NSIZE - 1) - bj0];
        float2 gm1 = grow[-1];
        float2 gm2 = grow[-2];
        #pragma unroll 4
        for (int bi = 0; bi < NSIZE; bi += 2) {
            float4 mm = mrow4[bi >> 1];          // broadcast: 2 modes at once
            float2 g0 = grow[bi];
            r0 = fmaf(mm.x, g0.x,  r0); r0 = fmaf(-mm.y, g0.y,  r0);
            i0 = fmaf(mm.x, g0.y,  i0); i0 = fmaf( mm.y, g0.x,  i0);
            r1 = fmaf(mm.x, gm1.x, r1); r1 = fmaf(-mm.y, gm1.y, r1);
            i1 = fmaf(mm.x, gm1.y, i1); i1 = fmaf( mm.y, gm1.x, i1);
            r2 = fmaf(mm.x, gm2.x, r2); r2 = fmaf(-mm.y, gm2.y, r2);
            i2 = fmaf(mm.x, gm2.y, i2); i2 = fmaf( mm.y, gm2.x, i2);
            float2 g1 = grow[bi + 1];
            r0 = fmaf(mm.z, g1.x,  r0); r0 = fmaf(-mm.w, g1.y,  r0);
            i0 = fmaf(mm.z, g1.y,  i0); i0 = fmaf( mm.w, g1.x,  i0);
            r1 = fmaf(mm.z, g0.x,  r1); r1 = fmaf(-mm.w, g0.y,  r1);
            i1 = fmaf(mm.z, g0.y,  i1); i1 = fmaf( mm.w, g0.x,  i1);
            r2 = fmaf(mm.z, gm1.x, r2); r2 = fmaf(-mm.w, gm1.y, r2);
            i2 = fmaf(mm.z, gm1.y, i2); i2 = fmaf( mm.w, gm1.x, i2);
            gm2 = g0; gm1 = g1;                  // slide window by 2
        }
    }

    int base = blockIdx.y * MTOT + (aj0 + w) * NSIZE + bj0;
    d_part[base]     = make_float2(r0, i0);
    d_part[base + 1] = make_float2(r1, i1);
    d_part[base + 2] = make_float2(r2, i2);
}

// ---------------------------------------------------------------------------
// Fused reduce + output formatting (planar layout confirmed in round 5).
// ---------------------------------------------------------------------------
__global__ void reduce_planar(float* __restrict__ out) {
    int j = blockIdx.x * blockDim.x + threadIdx.x;
    if (j < MTOT) {
        float re = 0.f, im = 0.f;
        #pragma unroll
        for (int ch = 0; ch < CHUNKS; ch++) {
            float2 p = d_part[ch * MTOT + j];
            re += p.x; im += p.y;
        }
        out[j]        = re;
        out[MTOT + j] = im;
    }
}
__global__ void reduce_real(float* __restrict__ out) {
    int j = blockIdx.x * blockDim.x + threadIdx.x;
    if (j < MTOT) {
        float re = 0.f;
        #pragma unroll
        for (int ch = 0; ch < CHUNKS; ch++) re += d_part[ch * MTOT + j].x;
        out[j] = re;
    }
}
__global__ void reduce_interleaved(float2* __restrict__ out) {
    int j = blockIdx.x * blockDim.x + threadIdx.x;
    if (j < MTOT) {
        float re = 0.f, im = 0.f;
        #pragma unroll
        for (int ch = 0; ch < CHUNKS; ch++) {
            float2 p = d_part[ch * MTOT + j];
            re += p.x; im += p.y;
        }
        out[j] = make_float2(re, im);
    }
}

extern "C" void kernel_launch(void* const* d_in, const int* in_sizes, int n_in,
                              void* d_out, int out_size) {
    const float* x  = (const float*)d_in[0];
    const float* w  = (const float*)d_in[1];
    const float* xc = (const float*)d_in[2];
    const float* yc = (const float*)d_in[3];

    prep_fused<<<(2 * MTOT + 255) / 256, 256>>>(x, w, xc, yc);
    corr_kernel<<<dim3(NSIZE / AJT, CHUNKS), 128>>>();

    int blocks = (MTOT + 255) / 256;
    if (out_size == 2 * MTOT) {
        reduce_planar<<<blocks, 256>>>((float*)d_out);
    } else if (out_size == MTOT) {
        reduce_real<<<blocks, 256>>>((float*)d_out);
    } else {
        reduce_interleaved<<<blocks, 256>>>((float2*)d_out);
    }
}

// round 8
// speedup vs baseline: 1.7320x; 1.0010x over previous
#include <cuda_runtime.h>
#include <math.h>

#define NSIZE 96
#define MTOT  (NSIZE * NSIZE)        // 9216
#define GDIM  (2 * NSIZE - 1)        // 191
#define GTOT  (GDIM * GDIM)          // 36481
#define CHUNKS 16
#define CROWS  (NSIZE / CHUNKS)      // 6 source rows per block
#define AJT    4                     // aj values per block (one per warp)
#define GROWS  (CROWS + AJT - 1)     // 9 staged G rows

// Physics constants (match reference)
#define WAVELEN 1.55e-6
#define DZ      1.0e-5
#define TWO_PI  6.283185307179586476925286766559

typedef unsigned long long ull;

// packed f32x2 fma: d = a*b + c  (elementwise on 2 packed floats)
#define FFMA2(d, a, b, c) \
    asm("fma.rn.f32x2 %0, %1, %2, %3;" : "=l"(d) : "l"(a), "l"(b), "l"(c))
#define PACK2(d, lo, hi) \
    asm("mov.b64 %0, {%1, %2};" : "=l"(d) : "f"(lo), "f"(hi))
#define UNPACK2(lo, hi, s) \
    asm("mov.b64 {%0, %1}, %2;" : "=f"(lo), "=f"(hi) : "l"(s))

// Scratch in __device__ globals (no allocations allowed)
__device__ float2 d_modes[MTOT];
__device__ float2 d_G[GTOT];
__device__ float  d_part_re[CHUNKS * MTOT];
__device__ float  d_part_im[CHUNKS * MTOT];

// ---------------------------------------------------------------------------
// Fused prep.
//  threads [0, MTOT):      modes[i] = x[i]*exp(j*w[i])
//  threads [MTOT, 2*MTOT): one G QUADRANT entry (|da|,|db|), mirrored x4.
//  Phase: s = r/lambda computed in double via rsqrtf + one double Newton
//  (no sqrt.f64 / fp64 div sequences); angle = 2*pi*frac(s) in fp32 sincosf.
//  Amplitudes in fp32 (reference itself is fp32).
// ---------------------------------------------------------------------------
__global__ void prep_fused(const float* __restrict__ x,
                           const float* __restrict__ w,
                           const float* __restrict__ xc,
                           const float* __restrict__ yc) {
    int i = blockIdx.x * blockDim.x + threadIdx.x;
    if (i < MTOT) {
        float s, c;
        sincosf(w[i], &s, &c);
        float xv = x[i];
        d_modes[i] = make_float2(xv * c, xv * s);
        return;
    }
    int t = i - MTOT;
    if (t >= MTOT) return;
    int da = t / NSIZE;              // 0..95
    int db = t - da * NSIZE;         // 0..95

    const double inv_lam = 1.0 / WAVELEN;
    double ax = ((double)xc[da] - (double)xc[0]) * inv_lam;
    double ay = ((double)yc[db] - (double)yc[0]) * inv_lam;
    const double az = DZ * (1.0 / WAVELEN);
    double q = ax * ax + ay * ay + az * az;      // (r/lambda)^2, <= ~45000

    // s = sqrt(q) via fp32 rsqrt estimate + one double Newton step
    double y0 = (double)rsqrtf((float)q);
    double y1 = y0 * (1.5 - 0.5 * q * y0 * y0);  // rel err ~1e-13
    double s  = q * y1;                          // r/lambda
    double frac = s - trunc(s);
    float sn, cs;
    sincosf((float)(TWO_PI * frac), &sn, &cs);

    // amplitudes in fp32: ar = dz/(2*pi*r^3), ai = -dz/(lambda*r^2)
    float r2f  = (float)(q * (WAVELEN * WAVELEN));   // r^2 in m^2
    float invr = rsqrtf(r2f);                        // 1/r
    float inv_r2 = invr * invr;
    const float dAf = (float)(1.55e-6 * 1.55e-6);
    float ar = (float)(DZ / TWO_PI) * inv_r2 * invr;
    float ai = (float)(-DZ / WAVELEN) * inv_r2;
    float gr = (ar * cs - ai * sn) * dAf;
    float gi = (ar * sn + ai * cs) * dAf;
    float2 g = make_float2(gr, gi);

    int rp = (NSIZE - 1) + da, rm = (NSIZE - 1) - da;
    int cp = (NSIZE - 1) + db, cm = (NSIZE - 1) - db;
    d_G[rp * GDIM + cp] = g;
    d_G[rp * GDIM + cm] = g;
    d_G[rm * GDIM + cp] = g;
    d_G[rm * GDIM + cm] = g;
}

// ---------------------------------------------------------------------------
// Correlation with packed f32x2 FMA:
//   (r,i) += (mx,mx)*(gx,gy) + (my,my)*(-gy,gx)     [2 FFMA2 per cMAC]
// Block = 128 threads; warp w -> aj0+w; lane computes 3 consecutive bj via a
// sliding 2-deep G register window (packed + swapped forms kept in regs).
// ---------------------------------------------------------------------------
__global__ void __launch_bounds__(128) corr_kernel() {
    __shared__ __align__(16) float2 sm[CROWS * NSIZE];   // modes slab (6x96)
    __shared__ float2 sg[GROWS * GDIM];                  // G window   (9x191)

    int aj0 = blockIdx.x * AJT;
    int ai0 = blockIdx.y * CROWS;
    int tid = threadIdx.x;

    for (int t = tid; t < CROWS * NSIZE; t += 128)
        sm[t] = d_modes[ai0 * NSIZE + t];

    int row0 = ai0 - aj0 + (NSIZE - 1) - (AJT - 1);
    for (int t = tid; t < GROWS * GDIM; t += 128) {
        int ci = t / GDIM;
        int cc = t - ci * GDIM;
        sg[t] = d_G[(row0 + ci) * GDIM + cc];
    }
    __syncthreads();

    int w    = tid >> 5;
    int lane = tid & 31;
    int bj0  = lane * 3;

    ull acc0 = 0ull, acc1 = 0ull, acc2 = 0ull;   // packed (re, im)

    #pragma unroll
    for (int ci = 0; ci < CROWS; ci++) {
        const float4* __restrict__ mrow4 = (const float4*)&sm[ci * NSIZE];
        const ull* __restrict__ grow =
            (const ull*)&sg[(ci + (AJT - 1) - w) * GDIM + (NSIZE - 1) - bj0];

        // init sliding window: g at relative cols -1, -2 (always in range)
        ull gm1 = grow[-1], gm2 = grow[-2];
        float glo, ghi;
        ull gm1s, gm2s;
        UNPACK2(glo, ghi, gm1); PACK2(gm1s, -ghi, glo);
        UNPACK2(glo, ghi, gm2); PACK2(gm2s, -ghi, glo);

        #pragma unroll 4
        for (int bi = 0; bi < NSIZE; bi += 2) {
            float4 mm = mrow4[bi >> 1];          // 2 modes, warp-broadcast
            ull g0 = grow[bi];
            ull g1 = grow[bi + 1];
            ull g0s, g1s;
            UNPACK2(glo, ghi, g0); PACK2(g0s, -ghi, glo);
            UNPACK2(glo, ghi, g1); PACK2(g1s, -ghi, glo);
            ull mxx, myy, mzz, mww;
            PACK2(mxx, mm.x, mm.x); PACK2(myy, mm.y, mm.y);
            PACK2(mzz, mm.z, mm.z); PACK2(mww, mm.w, mm.w);

            // mode (mx,my) pairs with g0 / gm1 / gm2
            FFMA2(acc0, mxx, g0,   acc0); FFMA2(acc0, myy, g0s,  acc0);
            FFMA2(acc1, mxx, gm1,  acc1); FFMA2(acc1, myy, gm1s, acc1);
            FFMA2(acc2, mxx, gm2,  acc2); FFMA2(acc2, myy, gm2s, acc2);
            // mode (mz,mw) pairs with g1 / g0 / gm1
            FFMA2(acc0, mzz, g1,   acc0); FFMA2(acc0, mww, g1s,  acc0);
            FFMA2(acc1, mzz, g0,   acc1); FFMA2(acc1, mww, g0s,  acc1);
            FFMA2(acc2, mzz, gm1,  acc2); FFMA2(acc2, mww, gm1s, acc2);

            gm2 = g0; gm2s = g0s;                // slide window by 2
            gm1 = g1; gm1s = g1s;
        }
    }

    int base = blockIdx.y * MTOT + (aj0 + w) * NSIZE + bj0;
    float r0, i0, r1, i1, r2, i2;
    UNPACK2(r0, i0, acc0);
    UNPACK2(r1, i1, acc1);
    UNPACK2(r2, i2, acc2);
    d_part_re[base]     = r0;  d_part_im[base]     = i0;
    d_part_re[base + 1] = r1;  d_part_im[base + 1] = i1;
    d_part_re[base + 2] = r2;  d_part_im[base + 2] = i2;
}

// ---------------------------------------------------------------------------
// Reduce (planar partials -> planar output). 2*MTOT threads, stride-1 loads.
// ---------------------------------------------------------------------------
__global__ void reduce_planar(float* __restrict__ out) {
    int t = blockIdx.x * blockDim.x + threadIdx.x;
    if (t >= 2 * MTOT) return;
    const float* __restrict__ src = (t < MTOT) ? d_part_re : d_part_im;
    int j = (t < MTOT) ? t : t - MTOT;
    float acc = 0.f;
    #pragma unroll
    for (int ch = 0; ch < CHUNKS; ch++)
        acc += src[ch * MTOT + j];
    out[t] = acc;
}
__global__ void reduce_real(float* __restrict__ out) {
    int j = blockIdx.x * blockDim.x + threadIdx.x;
    if (j < MTOT) {
        float acc = 0.f;
        #pragma unroll
        for (int ch = 0; ch < CHUNKS; ch++) acc += d_part_re[ch * MTOT + j];
        out[j] = acc;
    }
}
__global__ void reduce_interleaved(float2* __restrict__ out) {
    int j = blockIdx.x * blockDim.x + threadIdx.x;
    if (j < MTOT) {
        float re = 0.f, im = 0.f;
        #pragma unroll
        for (int ch = 0; ch < CHUNKS; ch++) {
            re += d_part_re[ch * MTOT + j];
            im += d_part_im[ch * MTOT + j];
        }
        out[j] = make_float2(re, im);
    }
}

extern "C" void kernel_launch(void* const* d_in, const int* in_sizes, int n_in,
                              void* d_out, int out_size) {
    const float* x  = (const float*)d_in[0];
    const float* w  = (const float*)d_in[1];
    const float* xc = (const float*)d_in[2];
    const float* yc = (const float*)d_in[3];

    prep_fused<<<(2 * MTOT + 255) / 256, 256>>>(x, w, xc, yc);
    corr_kernel<<<dim3(NSIZE / AJT, CHUNKS), 128>>>();

    if (out_size == 2 * MTOT) {
        reduce_planar<<<(2 * MTOT + 255) / 256, 256>>>((float*)d_out);
    } else if (out_size == MTOT) {
        reduce_real<<<(MTOT + 255) / 256, 256>>>((float*)d_out);
    } else {
        reduce_interleaved<<<(MTOT + 255) / 256, 256>>>((float2*)d_out);
    }
}

// round 9
// speedup vs baseline: 1.8579x; 1.0727x over previous
#include <cuda_runtime.h>
#include <math.h>

#define NSIZE 96
#define MTOT  (NSIZE * NSIZE)        // 9216
#define GDIM  (2 * NSIZE - 1)        // 191
#define GTOT  (GDIM * GDIM)          // 36481
#define CHUNKS 16
#define CROWS  (NSIZE / CHUNKS)      // 6 source rows per chunk
#define AJT    4                     // aj values per block (one per warp)
#define GROWS  (CROWS + AJT - 1)     // 9 staged G rows
#define NBLOCKS (24 * CHUNKS)        // 384
#define NTHREADS 128

// Physics constants (match reference)
#define WAVELEN 1.55e-6
#define DZ      1.0e-5
#define TWO_PI  6.283185307179586476925286766559

// Scratch in __device__ globals (no allocations allowed)
__device__ float2 d_modes[MTOT];
__device__ float2 d_G[GTOT];
__device__ float  d_part_re[CHUNKS * MTOT];
__device__ float  d_part_im[CHUNKS * MTOT];
__device__ unsigned g_ctr[2];        // monotonic barrier tickets (never reset)

// Grid-wide barrier, replay-safe: tickets are monotonic across kernel
// launches; each arrival waits for the counter to reach the next multiple
// of NBLOCKS. Launches are serialized, so tickets of one replay are a
// contiguous block and the round-up target is exact.
__device__ __forceinline__ void grid_barrier(int i) {
    __syncthreads();
    if (threadIdx.x == 0) {
        __threadfence();
        unsigned ticket = atomicAdd(&g_ctr[i], 1u) + 1u;
        unsigned target = ((ticket + NBLOCKS - 1u) / NBLOCKS) * NBLOCKS;
        while (*(volatile unsigned*)&g_ctr[i] < target) { }
        __threadfence();
    }
    __syncthreads();
}

__global__ void __launch_bounds__(NTHREADS, 4)
fused_all(const float* __restrict__ x,
          const float* __restrict__ w,
          const float* __restrict__ xc,
          const float* __restrict__ yc,
          float* __restrict__ out, int out_size) {
    __shared__ __align__(16) float2 sm[CROWS * NSIZE];   // modes slab (6x96)
    __shared__ float2 sg[GROWS * GDIM];                  // G window   (9x191)

    int tid = threadIdx.x;
    int bx  = blockIdx.x;

    // ---------------- Phase A: prep (modes + G quadrant, mirrored x4) -----
    {
        int i = bx * NTHREADS + tid;
        if (i < MTOT) {
            float s, c;
            sincosf(w[i], &s, &c);
            float xv = x[i];
            d_modes[i] = make_float2(xv * c, xv * s);
        } else if (i < 2 * MTOT) {
            int t = i - MTOT;
            int da = t / NSIZE;
            int db = t - da * NSIZE;

            const double inv_lam = 1.0 / WAVELEN;
            double ax = ((double)xc[da] - (double)xc[0]) * inv_lam;
            double ay = ((double)yc[db] - (double)yc[0]) * inv_lam;
            const double az = DZ * (1.0 / WAVELEN);
            double q = ax * ax + ay * ay + az * az;      // (r/lambda)^2

            double y0 = (double)rsqrtf((float)q);
            double y1 = y0 * (1.5 - 0.5 * q * y0 * y0);  // Newton: ~1e-13
            double sdl  = q * y1;                        // r/lambda
            double frac = sdl - trunc(sdl);
            float sn, cs;
            sincosf((float)(TWO_PI * frac), &sn, &cs);

            float r2f  = (float)(q * (WAVELEN * WAVELEN));
            float invr = rsqrtf(r2f);
            float inv_r2 = invr * invr;
            const float dAf = (float)(1.55e-6 * 1.55e-6);
            float ar = (float)(DZ / TWO_PI) * inv_r2 * invr;
            float ai = (float)(-DZ / WAVELEN) * inv_r2;
            float2 g = make_float2((ar * cs - ai * sn) * dAf,
                                   (ar * sn + ai * cs) * dAf);

            int rp = (NSIZE - 1) + da, rm = (NSIZE - 1) - da;
            int cp = (NSIZE - 1) + db, cm = (NSIZE - 1) - db;
            d_G[rp * GDIM + cp] = g;
            d_G[rp * GDIM + cm] = g;
            d_G[rm * GDIM + cp] = g;
            d_G[rm * GDIM + cm] = g;
        }
    }

    grid_barrier(0);

    // ---------------- Phase B: correlation (R6 inner loop, best measured) -
    {
        int ajb = bx % (NSIZE / AJT);        // 0..23
        int ch  = bx / (NSIZE / AJT);        // 0..15
        int aj0 = ajb * AJT;
        int ai0 = ch * CROWS;

        for (int t = tid; t < CROWS * NSIZE; t += NTHREADS)
            sm[t] = d_modes[ai0 * NSIZE + t];

        int row0 = ai0 - aj0 + (NSIZE - 1) - (AJT - 1);
        for (int t = tid; t < GROWS * GDIM; t += NTHREADS) {
            int ci = t / GDIM;
            int cc = t - ci * GDIM;
            sg[t] = d_G[(row0 + ci) * GDIM + cc];
        }
        __syncthreads();

        int ww   = tid >> 5;
        int lane = tid & 31;
        int bj0  = lane * 3;

        float r0 = 0.f, i0 = 0.f, r1 = 0.f, i1 = 0.f, r2 = 0.f, i2 = 0.f;

        #pragma unroll
        for (int ci = 0; ci < CROWS; ci++) {
            const float2* __restrict__ mrow = &sm[ci * NSIZE];
            const float2* __restrict__ grow =
                &sg[(ci + (AJT - 1) - ww) * GDIM + (NSIZE - 1) - bj0];
            float2 gm1 = grow[-1];
            float2 gm2 = grow[-2];
            #pragma unroll 8
            for (int bi = 0; bi < NSIZE; bi++) {
                float2 g0 = grow[bi];
                float2 m  = mrow[bi];
                r0 = fmaf(m.x, g0.x,  r0); r0 = fmaf(-m.y, g0.y,  r0);
                i0 = fmaf(m.x, g0.y,  i0); i0 = fmaf( m.y, g0.x,  i0);
                r1 = fmaf(m.x, gm1.x, r1); r1 = fmaf(-m.y, gm1.y, r1);
                i1 = fmaf(m.x, gm1.y, i1); i1 = fmaf( m.y, gm1.x, i1);
                r2 = fmaf(m.x, gm2.x, r2); r2 = fmaf(-m.y, gm2.y, r2);
                i2 = fmaf(m.x, gm2.y, i2); i2 = fmaf( m.y, gm2.x, i2);
                gm2 = gm1; gm1 = g0;
            }
        }

        int base = ch * MTOT + (aj0 + ww) * NSIZE + bj0;
        d_part_re[base]     = r0;  d_part_im[base]     = i0;
        d_part_re[base + 1] = r1;  d_part_im[base + 1] = i1;
        d_part_re[base + 2] = r2;  d_part_im[base + 2] = i2;
    }

    grid_barrier(1);

    // ---------------- Phase C: reduce + format ---------------------------
    {
        int t = bx * NTHREADS + tid;
        if (out_size == 2 * MTOT) {
            if (t < 2 * MTOT) {
                const float* __restrict__ src =
                    (t < MTOT) ? d_part_re : d_part_im;
                int j = (t < MTOT) ? t : t - MTOT;
                float acc = 0.f;
                #pragma unroll
                for (int ch = 0; ch < CHUNKS; ch++)
                    acc += src[ch * MTOT + j];
                out[t] = acc;
            }
        } else if (out_size == MTOT) {
            if (t < MTOT) {
                float acc = 0.f;
                #pragma unroll
                for (int ch = 0; ch < CHUNKS; ch++)
                    acc += d_part_re[ch * MTOT + t];
                out[t] = acc;
            }
        } else {
            if (t < MTOT) {
                float re = 0.f, im = 0.f;
                #pragma unroll
                for (int ch = 0; ch < CHUNKS; ch++) {
                    re += d_part_re[ch * MTOT + t];
                    im += d_part_im[ch * MTOT + t];
                }
                ((float2*)out)[t] = make_float2(re, im);
            }
        }
    }
}

extern "C" void kernel_launch(void* const* d_in, const int* in_sizes, int n_in,
                              void* d_out, int out_size) {
    const float* x  = (const float*)d_in[0];
    const float* w  = (const float*)d_in[1];
    const float* xc = (const float*)d_in[2];
    const float* yc = (const float*)d_in[3];

    fused_all<<<NBLOCKS, NTHREADS>>>(x, w, xc, yc, (float*)d_out, out_size);
}

// round 10
// speedup vs baseline: 1.9917x; 1.0720x over previous
#include <cuda_runtime.h>
#include <math.h>

#define NSIZE 96
#define MTOT  (NSIZE * NSIZE)        // 9216
#define GDIM  (2 * NSIZE - 1)        // 191
#define GTOT  (GDIM * GDIM)          // 36481
#define CHUNKS 32
#define CROWS  (NSIZE / CHUNKS)      // 3 source rows per chunk
#define AJT    4                     // aj values per block (one per warp)
#define GROWS  (CROWS + AJT - 1)     // 6 staged G rows
#define NBLOCKS (24 * CHUNKS)        // 768
#define NTHREADS 128

// Physics constants (match reference)
#define WAVELEN 1.55e-6
#define DZ      1.0e-5
#define TWO_PI  6.283185307179586476925286766559
#define TWO_PI_F 6.2831853071795864769f
// (dz/lambda)^2 computed in extended precision
#define AZ2_F  41.62330905306972f

// Scratch in __device__ globals (no allocations allowed)
__device__ float2 d_modes[MTOT];
__device__ float2 d_G[GTOT];
__device__ float  d_part_re[CHUNKS * MTOT];
__device__ float  d_part_im[CHUNKS * MTOT];
__device__ unsigned g_ctr[2];        // monotonic barrier tickets (never reset)

// Grid-wide barrier, replay-safe: tickets are monotonic across launches.
__device__ __forceinline__ void grid_barrier(int i) {
    __syncthreads();
    if (threadIdx.x == 0) {
        __threadfence();
        unsigned ticket = atomicAdd(&g_ctr[i], 1u) + 1u;
        unsigned target = ((ticket + NBLOCKS - 1u) / NBLOCKS) * NBLOCKS;
        while (*(volatile unsigned*)&g_ctr[i] < target) { }
        __threadfence();
    }
    __syncthreads();
}

__global__ void __launch_bounds__(NTHREADS, 6)
fused_all(const float* __restrict__ x,
          const float* __restrict__ w,
          const float* __restrict__ xc,
          const float* __restrict__ yc,
          float* __restrict__ out, int out_size) {
    __shared__ __align__(16) float2 sm[CROWS * NSIZE];   // modes slab (3x96)
    __shared__ float2 sg[GROWS * GDIM];                  // G window   (6x191)

    int tid = threadIdx.x;
    int bx  = blockIdx.x;

    // ---------------- Phase A: prep (all fp32; no fp64 anywhere) ----------
    {
        int i = bx * NTHREADS + tid;
        if (i < MTOT) {
            float s, c;
            sincosf(w[i], &s, &c);
            float xv = x[i];
            d_modes[i] = make_float2(xv * c, xv * s);
        } else if (i < 2 * MTOT) {
            int t = i - MTOT;
            int da = t / NSIZE;
            int db = t - da * NSIZE;

            const float inv_lam = (float)(1.0 / WAVELEN);
            float ax = (xc[da] - xc[0]) * inv_lam;   // ~= da
            float ay = (yc[db] - yc[0]) * inv_lam;   // ~= db
            float q  = fmaf(ax, ax, fmaf(ay, ay, AZ2_F));  // (r/lambda)^2

            // frac(sqrt(q)) with FMA-cancellation Newton refinement:
            // s = s0 + e/(2 s0), e = q - s0^2 computed exactly via fmaf.
            float s0 = sqrtf(q);
            float e  = fmaf(-s0, s0, q);
            float ds = e / (2.0f * s0);
            float frac = (s0 - truncf(s0)) + ds;
            float sn, cs;
            sincosf(TWO_PI_F * frac, &sn, &cs);

            // amplitudes: ar = dz/(2 pi r^3), ai = -dz/(lambda r^2)
            float r2f  = q * (float)(WAVELEN * WAVELEN);
            float invr = rsqrtf(r2f);
            float inv_r2 = invr * invr;
            const float dAf = (float)(1.55e-6 * 1.55e-6);
            float ar = (float)(DZ / TWO_PI) * inv_r2 * invr;
            float ai = (float)(-DZ / WAVELEN) * inv_r2;
            float2 g = make_float2((ar * cs - ai * sn) * dAf,
                                   (ar * sn + ai * cs) * dAf);

            int rp = (NSIZE - 1) + da, rm = (NSIZE - 1) - da;
            int cp = (NSIZE - 1) + db, cm = (NSIZE - 1) - db;
            d_G[rp * GDIM + cp] = g;
            d_G[rp * GDIM + cm] = g;
            d_G[rm * GDIM + cp] = g;
            d_G[rm * GDIM + cm] = g;
        }
    }

    grid_barrier(0);

    // ---------------- Phase B: correlation (R6 inner loop, best measured) -
    {
        int ajb = bx % (NSIZE / AJT);        // 0..23
        int ch  = bx / (NSIZE / AJT);        // 0..31
        int aj0 = ajb * AJT;
        int ai0 = ch * CROWS;

        for (int t = tid; t < CROWS * NSIZE; t += NTHREADS)
            sm[t] = d_modes[ai0 * NSIZE + t];

        int row0 = ai0 - aj0 + (NSIZE - 1) - (AJT - 1);
        for (int t = tid; t < GROWS * GDIM; t += NTHREADS) {
            int ci = t / GDIM;
            int cc = t - ci * GDIM;
            sg[t] = d_G[(row0 + ci) * GDIM + cc];
        }
        __syncthreads();

        int ww   = tid >> 5;
        int lane = tid & 31;
        int bj0  = lane * 3;

        float r0 = 0.f, i0 = 0.f, r1 = 0.f, i1 = 0.f, r2 = 0.f, i2 = 0.f;

        #pragma unroll
        for (int ci = 0; ci < CROWS; ci++) {
            const float2* __restrict__ mrow = &sm[ci * NSIZE];
            const float2* __restrict__ grow =
                &sg[(ci + (AJT - 1) - ww) * GDIM + (NSIZE - 1) - bj0];
            float2 gm1 = grow[-1];
            float2 gm2 = grow[-2];
            #pragma unroll 8
            for (int bi = 0; bi < NSIZE; bi++) {
                float2 g0 = grow[bi];
                float2 m  = mrow[bi];
                r0 = fmaf(m.x, g0.x,  r0); r0 = fmaf(-m.y, g0.y,  r0);
                i0 = fmaf(m.x, g0.y,  i0); i0 = fmaf( m.y, g0.x,  i0);
                r1 = fmaf(m.x, gm1.x, r1); r1 = fmaf(-m.y, gm1.y, r1);
                i1 = fmaf(m.x, gm1.y, i1); i1 = fmaf( m.y, gm1.x, i1);
                r2 = fmaf(m.x, gm2.x, r2); r2 = fmaf(-m.y, gm2.y, r2);
                i2 = fmaf(m.x, gm2.y, i2); i2 = fmaf( m.y, gm2.x, i2);
                gm2 = gm1; gm1 = g0;
            }
        }

        int base = ch * MTOT + (aj0 + ww) * NSIZE + bj0;
        d_part_re[base]     = r0;  d_part_im[base]     = i0;
        d_part_re[base + 1] = r1;  d_part_im[base + 1] = i1;
        d_part_re[base + 2] = r2;  d_part_im[base + 2] = i2;
    }

    grid_barrier(1);

    // ---------------- Phase C: reduce + format ---------------------------
    {
        int t = bx * NTHREADS + tid;
        if (out_size == 2 * MTOT) {
            if (t < 2 * MTOT) {
                const float* __restrict__ src =
                    (t < MTOT) ? d_part_re : d_part_im;
                int j = (t < MTOT) ? t : t - MTOT;
                float acc = 0.f;
                #pragma unroll
                for (int ch = 0; ch < CHUNKS; ch++)
                    acc += src[ch * MTOT + j];
                out[t] = acc;
            }
        } else if (out_size == MTOT) {
            if (t < MTOT) {
                float acc = 0.f;
                #pragma unroll
                for (int ch = 0; ch < CHUNKS; ch++)
                    acc += d_part_re[ch * MTOT + t];
                out[t] = acc;
            }
        } else {
            if (t < MTOT) {
                float re = 0.f, im = 0.f;
                #pragma unroll
                for (int ch = 0; ch < CHUNKS; ch++) {
                    re += d_part_re[ch * MTOT + t];
                    im += d_part_im[ch * MTOT + t];
                }
                ((float2*)out)[t] = make_float2(re, im);
            }
        }
    }
}

extern "C" void kernel_launch(void* const* d_in, const int* in_sizes, int n_in,
                              void* d_out, int out_size) {
    const float* x  = (const float*)d_in[0];
    const float* w  = (const float*)d_in[1];
    const float* xc = (const float*)d_in[2];
    const float* yc = (const float*)d_in[3];

    fused_all<<<NBLOCKS, NTHREADS>>>(x, w, xc, yc, (float*)d_out, out_size);
}